// round 8
// baseline (speedup 1.0000x reference)
#include <cuda_runtime.h>
#include <cuda_fp16.h>
#include <math.h>
#include <stdint.h>

// Problem constants
#define HID   1024
#define N1C   28
#define N2C   280
#define N3C   2800
#define BMAX  4096

#define NCATC 640            // concat: W1(28) + W2(280) + W3[0:280] -> pad 640 (5 tiles)
#define ZANC0 308            // zcat col offset of z3 ancestors
#define N3P   2816           // level-3 rows padded (22 tiles)
#define NT1   5
#define NT2   22

#define BMt   256
#define NCH   16             // K chunks of 64 fp16 (128B) over K=1024

// ---------------------------------------------------------------------------
// Scratch (__device__ globals; allocation-free)
// ---------------------------------------------------------------------------
__device__ float g_zcat[BMAX * NCATC];     // z1 | z2 | z3_ancestors | pad
__device__ float g_z3[BMAX * N3C];         // fallback logits3 if d_out too small
__device__ float g_part[BMAX * NT2];       // per-(row, tile) exp-sum partials
__device__ float g_lossrows[BMAX];

__device__ alignas(256) __half g_xc  [BMAX  * HID];
__device__ alignas(256) __half g_wcat[NCATC * HID];
__device__ alignas(256) __half g_w3c [N3P   * HID];
__device__ float g_bcat[NCATC];

// ---------------------------------------------------------------------------
// helpers
// ---------------------------------------------------------------------------
__device__ __forceinline__ uint32_t smem_u32(const void* p) {
    uint32_t a;
    asm("{ .reg .u64 t; cvta.to.shared.u64 t, %1; cvt.u32.u64 %0, t; }" : "=r"(a) : "l"(p));
    return a;
}
#define SWZ(off) ((off) ^ (((off) >> 3) & 0x70))

#define CP16(dst, src) \
    asm volatile("cp.async.cg.shared.global [%0], [%1], 16;" :: "r"(dst), "l"(src))
#define CP_COMMIT() asm volatile("cp.async.commit_group;" ::: "memory")
#define CP_WAIT(n)  asm volatile("cp.async.wait_group %0;" :: "n"(n) : "memory")

#define LDSM4(r0, r1, r2, r3, addr) \
    asm volatile("ldmatrix.sync.aligned.m8n8.x4.shared.b16 {%0,%1,%2,%3}, [%4];" \
                 : "=r"(r0), "=r"(r1), "=r"(r2), "=r"(r3) : "r"(addr))

#define MMA16816(d, a, b) \
    asm volatile("mma.sync.aligned.m16n8k16.row.col.f32.f16.f16.f32 " \
                 "{%0,%1,%2,%3}, {%4,%5,%6,%7}, {%8,%9}, {%0,%1,%2,%3};" \
                 : "+f"((d)[0]), "+f"((d)[1]), "+f"((d)[2]), "+f"((d)[3]) \
                 : "r"((a)[0]), "r"((a)[1]), "r"((a)[2]), "r"((a)[3]), \
                   "r"((b)[0]), "r"((b)[1]))

__device__ __forceinline__ float sigmoid_fast(float v) {
    return 1.f / (1.f + __expf(-v));
}

// ---------------------------------------------------------------------------
// Conversion: blocks [0,B): x rows; [B,B+640): Wcat rows; then W3 rows; last: bcat
// ---------------------------------------------------------------------------
__global__ __launch_bounds__(256)
void convert_all_kernel(const float* __restrict__ x,
                        const float* __restrict__ W1, const float* __restrict__ b1,
                        const float* __restrict__ W2, const float* __restrict__ b2,
                        const float* __restrict__ W3, const float* __restrict__ b3,
                        __half* __restrict__ xc, __half* __restrict__ wcat,
                        __half* __restrict__ w3c, float* __restrict__ bcat,
                        int B)
{
    int blk = blockIdx.x;
    int t = threadIdx.x;

    if (blk == B + NCATC + N3P) {          // bias concat block
        for (int j = t; j < NCATC; j += 256) {
            float v = 0.f;
            if (j < N1C)            v = b1[j];
            else if (j < ZANC0)     v = b2[j - N1C];
            else if (j < ZANC0+280) v = b3[j - ZANC0];
            bcat[j] = v;
        }
        return;
    }

    const float* src = nullptr; __half* dst; int srow, drow;
    if (blk < B) { src = x; dst = xc; srow = blk; drow = blk; }
    else if (blk < B + NCATC) {
        int r = blk - B; dst = wcat; drow = r;
        if (r < N1C)              { src = W1; srow = r; }
        else if (r < ZANC0)       { src = W2; srow = r - N1C; }
        else if (r < ZANC0 + 280) { src = W3; srow = r - ZANC0; }
        else                      { srow = 0; }
    } else {
        int r = blk - B - NCATC; dst = w3c; drow = r;
        if (r < N3C) { src = W3; srow = r; } else { srow = 0; }
    }

    int k4 = t * 4;
    float4 v = make_float4(0.f, 0.f, 0.f, 0.f);
    if (src) v = *(const float4*)(src + (size_t)srow * HID + k4);
    __half2* d2 = (__half2*)(dst + (size_t)drow * HID + k4);
    d2[0] = __half2{__float2half_rn(v.x), __float2half_rn(v.y)};
    d2[1] = __half2{__float2half_rn(v.z), __float2half_rn(v.w)};
}

// ---------------------------------------------------------------------------
// GEMM: CTA 256x128, 512 threads, 16 warps (4M x 4N, warp tile 64x32), 4 stages.
// PHASE 1: out = sigmoid(x@Wcat^T + bcat) -> zcat [B,640]
// PHASE 2: logits3 = zanc[c/100]*zanc[c/10]*sigmoid(x@W3^T+b3); + expsum partials
// ---------------------------------------------------------------------------
#define ASTG 32768u
#define BSTG 16384u
#define B_OFF (4u * ASTG)
#define SMEM_BYTES (1024u + 4u * ASTG + 4u * BSTG)   // 197632

template <int PHASE>
__global__ __launch_bounds__(512, 1)
void gemm_kernel(const __half* __restrict__ xc,
                 const __half* __restrict__ W, const float* __restrict__ bias,
                 float* __restrict__ out,
                 const float* __restrict__ zcat,      // PHASE2: ancestors
                 float* __restrict__ part)            // PHASE2: partial expsums
{
    extern __shared__ char smem[];
    const uint32_t sb = (smem_u32(smem) + 1023u) & ~1023u;

    const int tid  = threadIdx.x;
    const int lane = tid & 31;
    const int w    = tid >> 5;
    const int m0   = blockIdx.y * BMt;
    const int n0   = blockIdx.x * 128;
    const int Nst  = (PHASE == 1) ? NCATC : N3C;

    const char* Abase = (const char*)(xc + (size_t)m0 * HID);    // 2048 B/row
    const char* Bbase = (const char*)(W  + (size_t)n0 * HID);    // 2048 B/row

    auto issue_loads = [&](int c) {
        const uint32_t Ast = sb + (uint32_t)(c & 3) * ASTG;
        const int coff = c * 128;
#pragma unroll
        for (int it = 0; it < 4; it++) {
            int i = tid + it * 512;                  // 0..2047 (A: 256 rows)
            int row = i >> 3;
            int seg = (i & 7) * 16;
            CP16(Ast + SWZ((uint32_t)(row * 128 + seg)),
                 Abase + (size_t)row * 2048 + coff + seg);
        }
        const uint32_t Bst = sb + B_OFF + (uint32_t)(c & 3) * BSTG;
#pragma unroll
        for (int it = 0; it < 2; it++) {
            int i = tid + it * 512;                  // 0..1023 (B: 128 rows)
            int row = i >> 3;
            int seg = (i & 7) * 16;
            CP16(Bst + SWZ((uint32_t)(row * 128 + seg)),
                 Bbase + (size_t)row * 2048 + coff + seg);
        }
        CP_COMMIT();
    };

    const int warpM = w & 3;
    const int warpN = w >> 2;
    const int m0w = warpM * 64;
    const int n0w = warpN * 32;

    const uint32_t aRow = (uint32_t)((m0w + (lane & 15)) * 128 + (lane >> 4) * 16);
    const uint32_t bRow = (uint32_t)((n0w + (lane & 15)) * 128 + (lane >> 4) * 16);

    float acc[4][4][4];
#pragma unroll
    for (int i = 0; i < 4; i++)
#pragma unroll
        for (int j = 0; j < 4; j++)
#pragma unroll
            for (int r = 0; r < 4; r++) acc[i][j][r] = 0.f;

    issue_loads(0); issue_loads(1); issue_loads(2);

    for (int c = 0; c < NCH; c++) {
        if (c < NCH - 2)      { CP_WAIT(2); }
        else if (c == NCH - 2){ CP_WAIT(1); }
        else                  { CP_WAIT(0); }
        __syncthreads();

        if (c + 3 < NCH) issue_loads(c + 3);

        const uint32_t Ast = sb + (uint32_t)(c & 3) * ASTG;
        const uint32_t Bst = sb + B_OFF + (uint32_t)(c & 3) * BSTG;

#pragma unroll
        for (int ks = 0; ks < 4; ks++) {
            uint32_t a[4][4];
#pragma unroll
            for (int i = 0; i < 4; i++) {
                uint32_t ad = Ast + SWZ(aRow + (uint32_t)(i * 2048 + ks * 32));
                LDSM4(a[i][0], a[i][1], a[i][2], a[i][3], ad);
            }
            uint32_t bf[4][2];
#pragma unroll
            for (int jj = 0; jj < 2; jj++) {
                uint32_t bd = Bst + SWZ(bRow + (uint32_t)(jj * 2048 + ks * 32));
                uint32_t r0, r1, r2, r3;
                LDSM4(r0, r1, r2, r3, bd);
                bf[2*jj][0]   = r0; bf[2*jj][1]   = r2;
                bf[2*jj+1][0] = r1; bf[2*jj+1][1] = r3;
            }
#pragma unroll
            for (int i = 0; i < 4; i++)
#pragma unroll
                for (int j = 0; j < 4; j++)
                    MMA16816(acc[i][j], a[i], bf[j]);
        }
        __syncthreads();
    }

    if (PHASE == 1) {
#pragma unroll
        for (int i = 0; i < 4; i++) {
            int row = m0 + m0w + i * 16 + (lane >> 2);
#pragma unroll
            for (int j = 0; j < 4; j++) {
                int col = n0 + n0w + j * 8 + (lane & 3) * 2;
                float bv0 = bias[col], bv1 = bias[col + 1];
                float2 v0, v1;
                v0.x = sigmoid_fast(acc[i][j][0] + bv0);
                v0.y = sigmoid_fast(acc[i][j][1] + bv1);
                v1.x = sigmoid_fast(acc[i][j][2] + bv0);
                v1.y = sigmoid_fast(acc[i][j][3] + bv1);
                *(float2*)(out + (size_t)row * Nst + col)       = v0;
                *(float2*)(out + (size_t)(row + 8) * Nst + col) = v1;
            }
        }
    } else {
        // fused transform: logit = zanc[c/100]*zanc[c/10]*sigmoid, + expsums
        float esum[4][2];
#pragma unroll
        for (int i = 0; i < 4; i++) { esum[i][0] = 0.f; esum[i][1] = 0.f; }

#pragma unroll
        for (int i = 0; i < 4; i++) {
            int rloc = m0w + i * 16 + (lane >> 2);
#pragma unroll
            for (int j = 0; j < 4; j++) {
                int col = n0 + n0w + j * 8 + (lane & 3) * 2;
                if (col < N3C) {
                    float bv0 = bias[col], bv1 = bias[col + 1];
                    int a100 = col / 100, a10a = col / 10, a10b = (col + 1) / 10;
#pragma unroll
                    for (int h = 0; h < 2; h++) {
                        int grow = m0 + rloc + h * 8;
                        const float* zr = zcat + (size_t)grow * NCATC + ZANC0;
                        float anc100 = __ldg(zr + a100);
                        float l0 = anc100 * __ldg(zr + a10a) *
                                   sigmoid_fast(acc[i][j][2*h]     + bv0);
                        float l1 = anc100 * __ldg(zr + a10b) *
                                   sigmoid_fast(acc[i][j][2*h + 1] + bv1);
                        *(float2*)(out + (size_t)grow * Nst + col) = float2{l0, l1};
                        esum[i][h] += __expf(l0) + __expf(l1);
                    }
                }
            }
        }

        // per-row reduction: quad shuffle, then across 4 N-warps via smem
        float* sm_part = (float*)(smem + (sb - smem_u32(smem)));  // 256 x 4 floats
#pragma unroll
        for (int i = 0; i < 4; i++)
#pragma unroll
            for (int h = 0; h < 2; h++) {
                float s = esum[i][h];
                s += __shfl_xor_sync(0xFFFFFFFFu, s, 1);
                s += __shfl_xor_sync(0xFFFFFFFFu, s, 2);
                if ((lane & 3) == 0) {
                    int rloc = m0w + i * 16 + (lane >> 2) + h * 8;
                    sm_part[rloc * 4 + warpN] = s;
                }
            }
        __syncthreads();
        if (tid < BMt) {
            float s = sm_part[tid * 4 + 0] + sm_part[tid * 4 + 1]
                    + sm_part[tid * 4 + 2] + sm_part[tid * 4 + 3];
            part[(size_t)(m0 + tid) * NT2 + blockIdx.x] = s;
        }
    }
}

// ---------------------------------------------------------------------------
// Loss kernel: one WARP per row (8 rows per 256-thr block). No smem, no bar.
// ---------------------------------------------------------------------------
__global__ __launch_bounds__(256)
void loss_kernel(const float* __restrict__ zcat,
                 const float* __restrict__ part,
                 const float* __restrict__ logits3,
                 const int*   __restrict__ labels,
                 float* __restrict__ loss_rows)
{
    const int lane = threadIdx.x & 31;
    const int b = blockIdx.x * 8 + (threadIdx.x >> 5);

    const float* zrow = zcat + (size_t)b * NCATC;

    float e1 = (lane < N1C) ? __expf(__ldg(zrow + lane)) : 0.f;

    float e2 = 0.f;
#pragma unroll
    for (int it = 0; it < 9; it++) {
        int k = lane + it * 32;
        if (k < N2C)
            e2 += __expf(__ldg(zrow + N1C + k / 10) * __ldg(zrow + N1C + k));
    }

    float e3 = (lane < NT2) ? __ldg(part + (size_t)b * NT2 + lane) : 0.f;

#pragma unroll
    for (int off = 16; off; off >>= 1) {
        e1 += __shfl_xor_sync(0xFFFFFFFFu, e1, off);
        e2 += __shfl_xor_sync(0xFFFFFFFFu, e2, off);
        e3 += __shfl_xor_sync(0xFFFFFFFFu, e3, off);
    }

    if (lane == 0) {
        int lab  = labels[b];
        int lab1 = lab / 100;
        int lab2 = lab / 10;
        float loss1 = logf(e1) - __ldg(zrow + lab1);
        float loss2 = logf(e2) - __ldg(zrow + N1C + lab2 / 10) * __ldg(zrow + N1C + lab2);
        float loss3 = logf(e3) - __ldg(logits3 + (size_t)b * N3C + lab);
        loss_rows[b] = loss1 + loss2 + loss3;
    }
}

__global__ __launch_bounds__(1024)
void loss_reduce_kernel(const float* __restrict__ lr, float* __restrict__ dst, int B)
{
    __shared__ float red[32];
    int t = threadIdx.x;
    float sv = 0.f;
    for (int i = t * 4; i < B; i += 4096) {
        float4 v = *(const float4*)(lr + i);
        sv += v.x + v.y + v.z + v.w;
    }
#pragma unroll
    for (int off = 16; off; off >>= 1) sv += __shfl_xor_sync(0xFFFFFFFFu, sv, off);
    if ((t & 31) == 0) red[t >> 5] = sv;
    __syncthreads();
    if (t == 0) {
        float tot = 0.f;
#pragma unroll
        for (int k = 0; k < 32; k++) tot += red[k];
        *dst = tot / (float)B;
    }
}

// ---------------------------------------------------------------------------
extern "C" void kernel_launch(void* const* d_in, const int* in_sizes, int n_in,
                              void* d_out, int out_size)
{
    const float* x      = (const float*)d_in[0];
    const int*   labels = (const int*)  d_in[1];
    const float* W1     = (const float*)d_in[2];
    const float* b1     = (const float*)d_in[3];
    const float* W2     = (const float*)d_in[4];
    const float* b2     = (const float*)d_in[5];
    const float* W3     = (const float*)d_in[6];
    const float* b3     = (const float*)d_in[7];

    int B = in_sizes[0] / HID;
    if (B > BMAX) B = BMAX;

    float* out = (float*)d_out;

    float *zcatp, *z3p, *partp, *lrp, *bcatp;
    __half *xcp, *wcatp, *w3p;
    cudaGetSymbolAddress((void**)&zcatp, g_zcat);
    cudaGetSymbolAddress((void**)&z3p,   g_z3);
    cudaGetSymbolAddress((void**)&partp, g_part);
    cudaGetSymbolAddress((void**)&lrp,   g_lossrows);
    cudaGetSymbolAddress((void**)&bcatp, g_bcat);
    cudaGetSymbolAddress((void**)&xcp,   g_xc);
    cudaGetSymbolAddress((void**)&wcatp, g_wcat);
    cudaGetSymbolAddress((void**)&w3p,   g_w3c);

    convert_all_kernel<<<B + NCATC + N3P + 1, 256>>>(
        x, W1, b1, W2, b2, W3, b3, xcp, wcatp, w3p, bcatp, B);

    const size_t LE = (size_t)B * N3C;
    float* zdst = ((size_t)out_size >= LE) ? out : z3p;

    cudaFuncSetAttribute(gemm_kernel<1>, cudaFuncAttributeMaxDynamicSharedMemorySize, SMEM_BYTES);
    cudaFuncSetAttribute(gemm_kernel<2>, cudaFuncAttributeMaxDynamicSharedMemorySize, SMEM_BYTES);

    gemm_kernel<1><<<dim3(NT1, B / BMt), 512, SMEM_BYTES>>>(
        xcp, wcatp, bcatp, zcatp, nullptr, nullptr);

    gemm_kernel<2><<<dim3(NT2, B / BMt), 512, SMEM_BYTES>>>(
        xcp, w3p, b3, zdst, zcatp, partp);

    loss_kernel<<<B / 8, 256>>>(zcatp, partp, zdst, labels, lrp);

    if ((size_t)out_size > LE) {
        loss_reduce_kernel<<<1, 1024>>>(lrp, out + LE, B);
    } else if ((size_t)out_size < LE && out_size >= 1) {
        loss_reduce_kernel<<<1, 1024>>>(lrp, out, B);
    }
}

// round 9
// speedup vs baseline: 1.1789x; 1.1789x over previous
#include <cuda_runtime.h>
#include <cuda_fp16.h>
#include <math.h>
#include <stdint.h>

// Problem constants
#define HID   1024
#define N1C   28
#define N2C   280
#define N3C   2800
#define BMAX  4096

#define NCATC 640            // concat cols: W1(28)|W2(280)|W3[0:280]|pad -> 5 tiles
#define ZANC0 308            // zcat col offset of level-3 ancestor z-values
#define NT1   5              // phase-1 column tiles
#define NT2   22             // phase-2 column tiles (2816 padded cols)
#define NTCOL (NT1 + NT2)    // 27

#define NCH   16             // K chunks of 64 fp16 (128B) over K=1024
#define MROWS (BMAX / 128)   // 32 row tiles

// ---------------------------------------------------------------------------
// Scratch (__device__ globals; allocation-free)
// ---------------------------------------------------------------------------
__device__ float g_zcat[BMAX * NCATC];
__device__ float g_z3[BMAX * N3C];          // fallback logits3 if d_out too small
__device__ float g_part[BMAX * NT2];        // per-(row, tile) exp-sum partials
__device__ float g_lossrows[BMAX];
__device__ int   g_flags[MROWS * 8];        // per-(row-tile, anc-tile) ready flags

__device__ alignas(256) __half g_xc  [BMAX  * HID];
__device__ alignas(256) __half g_wcat[NCATC * HID];
__device__ alignas(256) __half g_w3c [(NT2 * 128) * HID];
__device__ float g_bcat[NCATC];

// ---------------------------------------------------------------------------
// helpers
// ---------------------------------------------------------------------------
__device__ __forceinline__ uint32_t smem_u32(const void* p) {
    uint32_t a;
    asm("{ .reg .u64 t; cvta.to.shared.u64 t, %1; cvt.u32.u64 %0, t; }" : "=r"(a) : "l"(p));
    return a;
}
#define SWZ(off) ((off) ^ (((off) >> 3) & 0x70))

#define CP16(dst, src) \
    asm volatile("cp.async.cg.shared.global [%0], [%1], 16;" :: "r"(dst), "l"(src))
#define CP_COMMIT() asm volatile("cp.async.commit_group;" ::: "memory")
#define CP_WAIT(n)  asm volatile("cp.async.wait_group %0;" :: "n"(n) : "memory")

#define LDSM4(r0, r1, r2, r3, addr) \
    asm volatile("ldmatrix.sync.aligned.m8n8.x4.shared.b16 {%0,%1,%2,%3}, [%4];" \
                 : "=r"(r0), "=r"(r1), "=r"(r2), "=r"(r3) : "r"(addr))

#define MMA16816(d, a, b) \
    asm volatile("mma.sync.aligned.m16n8k16.row.col.f32.f16.f16.f32 " \
                 "{%0,%1,%2,%3}, {%4,%5,%6,%7}, {%8,%9}, {%0,%1,%2,%3};" \
                 : "+f"((d)[0]), "+f"((d)[1]), "+f"((d)[2]), "+f"((d)[3]) \
                 : "r"((a)[0]), "r"((a)[1]), "r"((a)[2]), "r"((a)[3]), \
                   "r"((b)[0]), "r"((b)[1]))

__device__ __forceinline__ float sigmoid_fast(float v) {
    return 1.f / (1.f + __expf(-v));
}

// ---------------------------------------------------------------------------
// Conversion + flag reset.
// blocks [0,B): x rows; [B,B+640): Wcat rows; then 2816 W3 rows; last: bcat+flags
// ---------------------------------------------------------------------------
__global__ __launch_bounds__(256)
void convert_all_kernel(const float* __restrict__ x,
                        const float* __restrict__ W1, const float* __restrict__ b1,
                        const float* __restrict__ W2, const float* __restrict__ b2,
                        const float* __restrict__ W3, const float* __restrict__ b3,
                        __half* __restrict__ xc, __half* __restrict__ wcat,
                        __half* __restrict__ w3c, float* __restrict__ bcat,
                        int* __restrict__ flags, int B)
{
    int blk = blockIdx.x;
    int t = threadIdx.x;
    const int NW3P = NT2 * 128;

    if (blk == B + NCATC + NW3P) {          // bias concat + flag reset block
        for (int j = t; j < NCATC; j += 256) {
            float v = 0.f;
            if (j < N1C)              v = b1[j];
            else if (j < ZANC0)       v = b2[j - N1C];
            else if (j < ZANC0 + 280) v = b3[j - ZANC0];
            bcat[j] = v;
        }
        if (t < MROWS * 8) flags[t] = 0;
        return;
    }

    const float* src = nullptr; __half* dst; int srow = 0, drow;
    if (blk < B) { src = x; dst = xc; srow = blk; drow = blk; }
    else if (blk < B + NCATC) {
        int r = blk - B; dst = wcat; drow = r;
        if (r < N1C)              { src = W1; srow = r; }
        else if (r < ZANC0)       { src = W2; srow = r - N1C; }
        else if (r < ZANC0 + 280) { src = W3; srow = r - ZANC0; }
    } else {
        int r = blk - B - NCATC; dst = w3c; drow = r;
        if (r < N3C) { src = W3; srow = r; }
    }

    int k4 = t * 4;
    float4 v = make_float4(0.f, 0.f, 0.f, 0.f);
    if (src) v = *(const float4*)(src + (size_t)srow * HID + k4);
    __half2* d2 = (__half2*)(dst + (size_t)drow * HID + k4);
    d2[0] = __half2{__float2half_rn(v.x), __float2half_rn(v.y)};
    d2[1] = __half2{__float2half_rn(v.z), __float2half_rn(v.w)};
}

// ---------------------------------------------------------------------------
// Unified GEMM: CTA 128x128, 256 threads, 8 warps (2M x 4N, warp 64x32),
// 3-stage cp.async, 2 CTAs/SM. grid = (27, B/128).
//   bx < 5 : zcat tile  -> sigmoid -> zcat; tiles 2..4 set ancestor flags
//   bx >= 5: level-3 tile -> wait flags -> fused transform + exp partials
// ---------------------------------------------------------------------------
#define STG   32768u          // A 16KB + B 16KB
#define SMEM_BYTES (1024u + 3u * STG)   // 99328

__global__ __launch_bounds__(256, 2)
void gemm_kernel(const __half* __restrict__ xc,
                 const __half* __restrict__ wcat, const float* __restrict__ bcat,
                 const __half* __restrict__ w3c,  const float* __restrict__ b3,
                 float* __restrict__ zcat, float* __restrict__ logits3,
                 float* __restrict__ part, int* __restrict__ flags)
{
    extern __shared__ char smem[];
    const uint32_t sb = (smem_u32(smem) + 1023u) & ~1023u;

    const int tid  = threadIdx.x;
    const int lane = tid & 31;
    const int w    = tid >> 5;
    const int bx   = blockIdx.x;
    const int by   = blockIdx.y;
    const int m0   = by * 128;
    const bool p1  = (bx < NT1);

    const __half* W  = p1 ? wcat : w3c;
    const float* bias = p1 ? bcat : b3;
    const int n0  = p1 ? bx * 128 : (bx - NT1) * 128;
    const int Nst = p1 ? NCATC : N3C;
    float* out = p1 ? zcat : logits3;

    const char* Abase = (const char*)(xc + (size_t)m0 * HID);
    const char* Bbase = (const char*)(W  + (size_t)n0 * HID);

    auto issue_loads = [&](int c) {
        const uint32_t st = sb + (uint32_t)(c % 3) * STG;
        const int coff = c * 128;
#pragma unroll
        for (int it = 0; it < 4; it++) {
            int i = tid + it * 256;                  // 0..1023 (A)
            int row = i >> 3;
            int seg = (i & 7) * 16;
            CP16(st + SWZ((uint32_t)(row * 128 + seg)),
                 Abase + (size_t)row * 2048 + coff + seg);
        }
#pragma unroll
        for (int it = 0; it < 4; it++) {
            int i = tid + it * 256;                  // 0..1023 (B)
            int row = i >> 3;
            int seg = (i & 7) * 16;
            CP16(st + 16384u + SWZ((uint32_t)(row * 128 + seg)),
                 Bbase + (size_t)row * 2048 + coff + seg);
        }
        CP_COMMIT();
    };

    const int warpM = w & 1;
    const int warpN = w >> 1;
    const int m0w = warpM * 64;
    const int n0w = warpN * 32;

    const uint32_t aRow = (uint32_t)((m0w + (lane & 15)) * 128 + (lane >> 4) * 16);
    const uint32_t bRow = (uint32_t)((n0w + (lane & 15)) * 128 + (lane >> 4) * 16);

    float acc[4][4][4];
#pragma unroll
    for (int i = 0; i < 4; i++)
#pragma unroll
        for (int j = 0; j < 4; j++)
#pragma unroll
            for (int r = 0; r < 4; r++) acc[i][j][r] = 0.f;

    issue_loads(0); issue_loads(1);

    for (int c = 0; c < NCH; c++) {
        if (c == NCH - 1) { CP_WAIT(0); } else { CP_WAIT(1); }
        __syncthreads();

        if (c + 2 < NCH) issue_loads(c + 2);

        const uint32_t Ast = sb + (uint32_t)(c % 3) * STG;
        const uint32_t Bst = Ast + 16384u;

#pragma unroll
        for (int ks = 0; ks < 4; ks++) {
            uint32_t a[4][4];
#pragma unroll
            for (int i = 0; i < 4; i++) {
                uint32_t ad = Ast + SWZ(aRow + (uint32_t)(i * 2048 + ks * 32));
                LDSM4(a[i][0], a[i][1], a[i][2], a[i][3], ad);
            }
            uint32_t bf[4][2];
#pragma unroll
            for (int jj = 0; jj < 2; jj++) {
                uint32_t bd = Bst + SWZ(bRow + (uint32_t)(jj * 2048 + ks * 32));
                uint32_t r0, r1, r2, r3;
                LDSM4(r0, r1, r2, r3, bd);
                bf[2*jj][0]   = r0; bf[2*jj][1]   = r2;
                bf[2*jj+1][0] = r1; bf[2*jj+1][1] = r3;
            }
#pragma unroll
            for (int i = 0; i < 4; i++)
#pragma unroll
                for (int j = 0; j < 4; j++)
                    MMA16816(acc[i][j], a[i], bf[j]);
        }
        __syncthreads();
    }

    if (p1) {
        // zcat epilogue: bias + sigmoid
#pragma unroll
        for (int i = 0; i < 4; i++) {
            int row = m0 + m0w + i * 16 + (lane >> 2);
#pragma unroll
            for (int j = 0; j < 4; j++) {
                int col = n0 + n0w + j * 8 + (lane & 3) * 2;
                float bv0 = bias[col], bv1 = bias[col + 1];
                float2 v0, v1;
                v0.x = sigmoid_fast(acc[i][j][0] + bv0);
                v0.y = sigmoid_fast(acc[i][j][1] + bv1);
                v1.x = sigmoid_fast(acc[i][j][2] + bv0);
                v1.y = sigmoid_fast(acc[i][j][3] + bv1);
                *(float2*)(out + (size_t)row * Nst + col)       = v0;
                *(float2*)(out + (size_t)(row + 8) * Nst + col) = v1;
            }
        }
        __syncthreads();                      // all stores issued
        if (tid == 0 && bx >= 2) {            // tiles 2..4 hold ancestors
            __threadfence();
            *((volatile int*)(flags + by * 8 + (bx - 2))) = 1;
        }
    } else {
        // wait for this row-block's ancestor tiles (zcat cols 256..639)
        if (tid < 3) {
            volatile int* f = flags + by * 8 + tid;
            while (*f == 0) { __nanosleep(64); }
        }
        __syncthreads();
        __threadfence();

        // fused transform: logit = zanc[c/100]*zanc[c/10]*sigmoid(acc+b) + expsums
        float esum[4][2];
#pragma unroll
        for (int i = 0; i < 4; i++) { esum[i][0] = 0.f; esum[i][1] = 0.f; }

#pragma unroll
        for (int i = 0; i < 4; i++) {
            int rloc = m0w + i * 16 + (lane >> 2);
#pragma unroll
            for (int j = 0; j < 4; j++) {
                int col = n0 + n0w + j * 8 + (lane & 3) * 2;
                if (col < N3C) {
                    float bv0 = bias[col], bv1 = bias[col + 1];
                    int a100 = col / 100, a10a = col / 10, a10b = (col + 1) / 10;
#pragma unroll
                    for (int h = 0; h < 2; h++) {
                        int grow = m0 + rloc + h * 8;
                        const float* zr = zcat + (size_t)grow * NCATC + ZANC0;
                        float anc100 = __ldg(zr + a100);
                        float l0 = anc100 * __ldg(zr + a10a) *
                                   sigmoid_fast(acc[i][j][2*h]     + bv0);
                        float l1 = anc100 * __ldg(zr + a10b) *
                                   sigmoid_fast(acc[i][j][2*h + 1] + bv1);
                        *(float2*)(out + (size_t)grow * Nst + col) = float2{l0, l1};
                        esum[i][h] += __expf(l0) + __expf(l1);
                    }
                }
            }
        }

        // per-row reduction: quad shuffle, then across 4 N-warps via smem
        float* sm_part = (float*)(smem + (sb - smem_u32(smem)));  // 128 x 4 floats
#pragma unroll
        for (int i = 0; i < 4; i++)
#pragma unroll
            for (int h = 0; h < 2; h++) {
                float s = esum[i][h];
                s += __shfl_xor_sync(0xFFFFFFFFu, s, 1);
                s += __shfl_xor_sync(0xFFFFFFFFu, s, 2);
                if ((lane & 3) == 0) {
                    int rloc = m0w + i * 16 + (lane >> 2) + h * 8;
                    sm_part[rloc * 4 + warpN] = s;
                }
            }
        __syncthreads();
        if (tid < 128) {
            float s = sm_part[tid * 4 + 0] + sm_part[tid * 4 + 1]
                    + sm_part[tid * 4 + 2] + sm_part[tid * 4 + 3];
            part[(size_t)(m0 + tid) * NT2 + (bx - NT1)] = s;
        }
    }
}

// ---------------------------------------------------------------------------
// Loss kernel: one WARP per row (8 rows per 256-thr block).
// ---------------------------------------------------------------------------
__global__ __launch_bounds__(256)
void loss_kernel(const float* __restrict__ zcat,
                 const float* __restrict__ part,
                 const float* __restrict__ logits3,
                 const int*   __restrict__ labels,
                 float* __restrict__ loss_rows)
{
    const int lane = threadIdx.x & 31;
    const int b = blockIdx.x * 8 + (threadIdx.x >> 5);

    const float* zrow = zcat + (size_t)b * NCATC;

    float e1 = (lane < N1C) ? __expf(__ldg(zrow + lane)) : 0.f;

    float e2 = 0.f;
#pragma unroll
    for (int it = 0; it < 9; it++) {
        int k = lane + it * 32;
        if (k < N2C)
            e2 += __expf(__ldg(zrow + N1C + k / 10) * __ldg(zrow + N1C + k));
    }

    float e3 = (lane < NT2) ? __ldg(part + (size_t)b * NT2 + lane) : 0.f;

#pragma unroll
    for (int off = 16; off; off >>= 1) {
        e1 += __shfl_xor_sync(0xFFFFFFFFu, e1, off);
        e2 += __shfl_xor_sync(0xFFFFFFFFu, e2, off);
        e3 += __shfl_xor_sync(0xFFFFFFFFu, e3, off);
    }

    if (lane == 0) {
        int lab  = labels[b];
        int lab1 = lab / 100;
        int lab2 = lab / 10;
        float loss1 = logf(e1) - __ldg(zrow + lab1);
        float loss2 = logf(e2) - __ldg(zrow + N1C + lab2 / 10) * __ldg(zrow + N1C + lab2);
        float loss3 = logf(e3) - __ldg(logits3 + (size_t)b * N3C + lab);
        loss_rows[b] = loss1 + loss2 + loss3;
    }
}

__global__ __launch_bounds__(1024)
void loss_reduce_kernel(const float* __restrict__ lr, float* __restrict__ dst, int B)
{
    __shared__ float red[32];
    int t = threadIdx.x;
    float sv = 0.f;
    for (int i = t * 4; i < B; i += 4096) {
        float4 v = *(const float4*)(lr + i);
        sv += v.x + v.y + v.z + v.w;
    }
#pragma unroll
    for (int off = 16; off; off >>= 1) sv += __shfl_xor_sync(0xFFFFFFFFu, sv, off);
    if ((t & 31) == 0) red[t >> 5] = sv;
    __syncthreads();
    if (t == 0) {
        float tot = 0.f;
#pragma unroll
        for (int k = 0; k < 32; k++) tot += red[k];
        *dst = tot / (float)B;
    }
}

// ---------------------------------------------------------------------------
extern "C" void kernel_launch(void* const* d_in, const int* in_sizes, int n_in,
                              void* d_out, int out_size)
{
    const float* x      = (const float*)d_in[0];
    const int*   labels = (const int*)  d_in[1];
    const float* W1     = (const float*)d_in[2];
    const float* b1     = (const float*)d_in[3];
    const float* W2     = (const float*)d_in[4];
    const float* b2     = (const float*)d_in[5];
    const float* W3     = (const float*)d_in[6];
    const float* b3     = (const float*)d_in[7];

    int B = in_sizes[0] / HID;
    if (B > BMAX) B = BMAX;

    float* out = (float*)d_out;

    float *zcatp, *z3p, *partp, *lrp, *bcatp;
    int* flagsp;
    __half *xcp, *wcatp, *w3p;
    cudaGetSymbolAddress((void**)&zcatp, g_zcat);
    cudaGetSymbolAddress((void**)&z3p,   g_z3);
    cudaGetSymbolAddress((void**)&partp, g_part);
    cudaGetSymbolAddress((void**)&lrp,   g_lossrows);
    cudaGetSymbolAddress((void**)&bcatp, g_bcat);
    cudaGetSymbolAddress((void**)&flagsp, g_flags);
    cudaGetSymbolAddress((void**)&xcp,   g_xc);
    cudaGetSymbolAddress((void**)&wcatp, g_wcat);
    cudaGetSymbolAddress((void**)&w3p,   g_w3c);

    convert_all_kernel<<<B + NCATC + NT2 * 128 + 1, 256>>>(
        x, W1, b1, W2, b2, W3, b3, xcp, wcatp, w3p, bcatp, flagsp, B);

    const size_t LE = (size_t)B * N3C;
    float* zdst = ((size_t)out_size >= LE) ? out : z3p;

    cudaFuncSetAttribute(gemm_kernel, cudaFuncAttributeMaxDynamicSharedMemorySize, SMEM_BYTES);

    gemm_kernel<<<dim3(NTCOL, B / 128), 256, SMEM_BYTES>>>(
        xcp, wcatp, bcatp, w3p, b3, zcatp, zdst, partp, flagsp);

    loss_kernel<<<B / 8, 256>>>(zcatp, partp, zdst, labels, lrp);

    if ((size_t)out_size > LE) {
        loss_reduce_kernel<<<1, 1024>>>(lrp, out + LE, B);
    } else if ((size_t)out_size < LE && out_size >= 1) {
        loss_reduce_kernel<<<1, 1024>>>(lrp, out, B);
    }
}